// round 17
// baseline (speedup 1.0000x reference)
#include <cuda_runtime.h>
#include <cuda.h>
#include <cstdint>

// ============================================================================
// MultiLoraLinear on GB300 (ptxas target = plain sm_103, so NO tcgen05).
// SINGLE kernel: compute warps first convert this batch's W fp32 -> f16 into
// a global scratch (grid-wide ticket sync; replay-safe monotonic counters),
// overlapped with the A-producer warp already streaming x via TMA. Then the
// usual TMA + mbarrier pipeline -> SMEM -> mma.sync m16n8k16 f16.
//   out[b, s, o] = sum_i x[b, s, i] * weight[adapter_ids[b], o, i]
// B=8, S=2048, IN=4096, OUT=64, L=16, fp32 in/out.
//
// R17 vs R16 (bench 55.4 = main 49.5 + 5.9 two-kernel overhead; DRAM 70% is
// the pattern's HBM ceiling -- main kernel is done):
//   Fuse the W-conversion prologue into the main kernel:
//   - 576 thr: warps 0-15 compute, warp 16 = A-TMA producer (starts at t=0),
//     warp 17 = W-TMA producer (gated on conversion flag).
//   - each CTA converts 1/16 of W[ids[b]] (8 float4/thread); cross-CTA sync
//     via ticket counters (atomicAdd; run index = ticket/16) -- safe across
//     graph replays; all 128 CTAs co-resident so spin cannot deadlock.
//   - stage barrier split fullA/fullW so x streaming overlaps conversion.
// ============================================================================

#define DEVINL __device__ __forceinline__

namespace mlora {

constexpr int kB = 8, kS = 2048, kIN = 4096, kOUT = 64, kL = 16;
constexpr int TILE_M = 128;           // x rows per CTA
constexpr int TILE_K = 64;            // K elems per pipeline stage
constexpr int NITER  = kIN / TILE_K;  // 64
constexpr int NSTAGE = 5;

// Each stage: A = [128 rows x 64 k] fp32 as two [128 x 32] sub-tiles
// (128B rows, TMA SW128); B(W) = [64 rows x 64 k] f16, ONE tile, 128B rows.
constexpr int A_SUB   = TILE_M * 32 * 4;        // 16384
constexpr int A_BYTES = 2 * A_SUB;              // 32768
constexpr int B_BYTES = kOUT * TILE_K * 2;      //  8192 (f16)
constexpr int STAGE_BYTES = A_BYTES + B_BYTES;  // 40960

constexpr int OFF_FULLA = 0;                    // 5 x 8
constexpr int OFF_FULLW = OFF_FULLA + NSTAGE * 8;
constexpr int OFF_EMPTY = OFF_FULLW + NSTAGE * 8;
constexpr int OFF_FLAG  = OFF_EMPTY + NSTAGE * 8;
constexpr int OFF_DATA  = 1024;                              // SW128 alignment
constexpr int SMEM_TOTAL = OFF_DATA + NSTAGE * STAGE_BYTES;  // 205824

constexpr int NTHREADS = 576;          // 16 compute warps + A-prod + W-prod
constexpr int W_ELEMS  = kL * kOUT * kIN;   // 4,194,304
constexpr int W_PER_AD = kOUT * kIN;        // 262,144 floats per adapter

}  // namespace mlora

// 8MB f16 scratch for converted weights ([L][OUT][IN], IN contiguous).
__device__ __align__(16) uint16_t g_wf16[mlora::W_ELEMS];
// Per-batch conversion-complete counters (monotonic across graph replays;
// the ticket scheme below derives the run index from the counter itself).
__device__ unsigned int g_done[mlora::kB];

namespace mlora {

DEVINL uint32_t smem_u32(const void* p) {
    uint32_t a;
    asm("{ .reg .u64 t; cvta.to.shared.u64 t, %1; cvt.u32.u64 %0, t; }"
        : "=r"(a) : "l"(p));
    return a;
}

DEVINL uint32_t elect_one() {
    uint32_t pred;
    asm volatile(
        "{\n\t.reg .pred p;\n\telect.sync _|p, 0xFFFFFFFF;\n\t"
        "selp.b32 %0, 1, 0, p;\n\t}"
        : "=r"(pred));
    return pred;
}

#define MBARRIER_INIT(mbar, count) \
    asm volatile("mbarrier.init.shared.b64 [%0], %1;" \
        :: "r"((uint32_t)(mbar)), "r"((uint32_t)(count)) : "memory")

#define MBARRIER_ARRIVE(mbar) \
    asm volatile("mbarrier.arrive.shared.b64 _, [%0];" \
        :: "r"((uint32_t)(mbar)) : "memory")

#define MBARRIER_EXPECT_TX(mbar, bytes) \
    asm volatile("mbarrier.arrive.expect_tx.shared.b64 _, [%0], %1;" \
        :: "r"((uint32_t)(mbar)), "r"((uint32_t)(bytes)) : "memory")

#define MBARRIER_WAIT_PARITY(mbar, parity) do {                                   \
    uint32_t _m = (uint32_t)(mbar);                                               \
    uint32_t _p = (uint32_t)(parity);                                             \
    uint32_t _done;                                                               \
    asm volatile(                                                                 \
        "{\n\t.reg .pred p;\n\t"                                                  \
        "mbarrier.try_wait.parity.acquire.cta.shared::cta.b64 p, [%1], %2;\n\t"   \
        "selp.b32 %0, 1, 0, p;\n\t}"                                              \
        : "=r"(_done) : "r"(_m), "r"(_p) : "memory");                             \
    if (!_done) {                                                                 \
        asm volatile(                                                             \
            "{\n\t.reg .pred P1;\n\t"                                             \
            "WAIT_LOOP_%=:\n\t"                                                   \
            "mbarrier.try_wait.parity.acquire.cta.shared::cta.b64 P1, [%0], %1, 0x989680;\n\t" \
            "@P1 bra.uni WAIT_DONE_%=;\n\t"                                       \
            "bra.uni WAIT_LOOP_%=;\n\t"                                           \
            "WAIT_DONE_%=:\n\t}"                                                  \
            :: "r"(_m), "r"(_p) : "memory");                                      \
    }                                                                             \
} while (0)

// Producer-side wait: post-wait SMEM writes are async-proxy (TMA) only.
#define MBARRIER_WAIT_PARITY_RELAXED(mbar, parity) do {                           \
    uint32_t _m = (uint32_t)(mbar);                                               \
    uint32_t _p = (uint32_t)(parity);                                             \
    uint32_t _done;                                                               \
    asm volatile(                                                                 \
        "{\n\t.reg .pred p;\n\t"                                                  \
        "mbarrier.try_wait.parity.relaxed.cta.shared::cta.b64 p, [%1], %2, 0x989680;\n\t" \
        "selp.b32 %0, 1, 0, p;\n\t}"                                              \
        : "=r"(_done) : "r"(_m), "r"(_p) : "memory");                             \
    if (!_done) {                                                                 \
        asm volatile(                                                             \
            "{\n\t.reg .pred P1;\n\t"                                             \
            "WAIT_LOOP_%=:\n\t"                                                   \
            "mbarrier.try_wait.parity.relaxed.cta.shared::cta.b64 P1, [%0], %1, 0x989680;\n\t" \
            "@P1 bra.uni WAIT_DONE_%=;\n\t"                                       \
            "bra.uni WAIT_LOOP_%=;\n\t"                                           \
            "WAIT_DONE_%=:\n\t}"                                                  \
            :: "r"(_m), "r"(_p) : "memory");                                      \
    }                                                                             \
} while (0)

#define TMA_LOAD_3D(smem_addr, tensor_map, cx, cy, cz, mbar) \
    asm volatile( \
        "cp.async.bulk.tensor.3d.shared::cta.global.tile.mbarrier::complete_tx::bytes " \
        "[%0], [%1, {%2, %3, %4}], [%5];" \
        :: "r"((uint32_t)(smem_addr)), "l"(tensor_map), \
           "r"((int32_t)(cx)), "r"((int32_t)(cy)), "r"((int32_t)(cz)), \
           "r"((uint32_t)(mbar)) \
        : "memory")

// Pack two f32 into one f16x2 register (rne): low half = vlo, high = vhi.
#define CVT_F16X2(dst, vlo, vhi) \
    asm("cvt.rn.f16x2.f32 %0, %1, %2;" : "=r"(dst) : "f"(vhi), "f"(vlo))

// m16n8k16 f16 MMA, fp32 accumulate (baseline PTX; fallback HMMA on sm_103).
#define MMA_F16(d, a, b) \
    asm volatile( \
        "mma.sync.aligned.m16n8k16.row.col.f32.f16.f16.f32 " \
        "{%0,%1,%2,%3}, {%4,%5,%6,%7}, {%8,%9}, {%0,%1,%2,%3};" \
        : "+f"((d)[0]), "+f"((d)[1]), "+f"((d)[2]), "+f"((d)[3]) \
        : "r"((a)[0]), "r"((a)[1]), "r"((a)[2]), "r"((a)[3]), \
          "r"((b)[0]), "r"((b)[1]))

// ============================================================================
// Kernel: 576 threads. Warps 0-15 compute: first convert this CTA's 1/16
// slice of W[ids[b]] fp32->f16 (rne, identical numerics), grid-sync via
// ticket counters, then warp w = (mh=w&3, kq=w>>2) owns rows [mh*32,+32) x
// all 64 cols over k16 slice kq per stage. Warp 16 = A-TMA producer (starts
// immediately). Warp 17 = W-TMA producer (gated on the conversion flag).
// grid = B * (S/128) = 128. blockIdx.x = b*16 + tile. 1 CTA per SM.
// ============================================================================
__global__ void __launch_bounds__(NTHREADS, 1) mlora_kernel(
    const __grid_constant__ CUtensorMap mapX,
    const __grid_constant__ CUtensorMap mapW,
    const int* __restrict__ adapter_ids,
    const float4* __restrict__ wsrc,
    float* __restrict__ out)
{
    extern __shared__ char smem[];
    const uint32_t sb = smem_u32(smem);
    const int tid  = threadIdx.x;
    const int wid  = tid >> 5;
    const int lid  = tid & 31;
    const int b    = blockIdx.x >> 4;
    const int tile = blockIdx.x & 15;

    if (tid == 0) {
        #pragma unroll
        for (int s = 0; s < NSTAGE; s++) {
            MBARRIER_INIT(sb + OFF_FULLA + s * 8, 1);   // completed by TMA tx bytes
            MBARRIER_INIT(sb + OFF_FULLW + s * 8, 1);
            MBARRIER_INIT(sb + OFF_EMPTY + s * 8, 16);  // 16 consumer warps arrive
        }
        asm volatile("st.shared.u32 [%0], %1;" :: "r"(sb + OFF_FLAG), "r"(0u)
                     : "memory");
    }
    __syncthreads();

    if (wid == 16) {
        // ---------------- A-TMA producer (independent of W) ----------------
        if (elect_one()) {
            int st = 0, ph = 1;  // parity 1: fresh empty barriers pass immediately
            for (int it = 0; it < NITER; it++) {
                MBARRIER_WAIT_PARITY_RELAXED(sb + OFF_EMPTY + st * 8, ph);
                MBARRIER_EXPECT_TX(sb + OFF_FULLA + st * 8, A_BYTES);
                const uint32_t base = sb + OFF_DATA + st * STAGE_BYTES;
                #pragma unroll
                for (int t = 0; t < 2; t++) {
                    TMA_LOAD_3D(base + t * A_SUB, &mapX,
                                it * TILE_K + t * 32, tile * TILE_M, b,
                                sb + OFF_FULLA + st * 8);
                }
                if (++st == NSTAGE) { st = 0; ph ^= 1; }
            }
        }
        return;
    }

    if (wid == 17) {
        // ---------------- W-TMA producer (gated on conversion) ----------------
        if (elect_one()) {
            // Wait for this CTA's conversion-sync flag.
            uint32_t f;
            do {
                asm volatile("ld.volatile.shared.u32 %0, [%1];"
                             : "=r"(f) : "r"(sb + OFF_FLAG));
            } while (!f);
            const int aid = adapter_ids[b];
            int st = 0, ph = 1;
            for (int it = 0; it < NITER; it++) {
                MBARRIER_WAIT_PARITY_RELAXED(sb + OFF_EMPTY + st * 8, ph);
                MBARRIER_EXPECT_TX(sb + OFF_FULLW + st * 8, B_BYTES);
                const uint32_t base = sb + OFF_DATA + st * STAGE_BYTES;
                TMA_LOAD_3D(base + A_BYTES, &mapW, it * TILE_K, 0, aid,
                            sb + OFF_FULLW + st * 8);
                if (++st == NSTAGE) { st = 0; ph ^= 1; }
            }
        }
        return;
    }

    // ======================= compute warps (wid 0..15) =======================

    // ---- Phase 1: convert this CTA's 1/16 slice of W[aid] fp32 -> f16 ----
    // (duplicate batches write identical bytes -- benign). 512 threads x
    // 8 float4 = 4096 float4 = the slice. rne conversion = same numerics as
    // converting at use.
    {
        const int aid = adapter_ids[b];
        const size_t adOff = (size_t)aid * (W_PER_AD / 4) + (size_t)tile * 4096;
        const float4* src = wsrc + adOff;
        uint2* dst = reinterpret_cast<uint2*>(g_wf16) + adOff;
        #pragma unroll
        for (int i = 0; i < 8; i++) {
            const int idx = tid + i * 512;
            const float4 v = src[idx];
            uint2 o;
            CVT_F16X2(o.x, v.x, v.y);
            CVT_F16X2(o.y, v.z, v.w);
            dst[idx] = o;
        }
        __threadfence();
        asm volatile("bar.sync 1, 512;" ::: "memory");   // CTA's slice done
        if (tid == 0) {
            // Ticket sync: run index = ticket/16 (replays are sequential, so
            // each run's 16 CTAs of batch b take 16 consecutive tickets).
            const unsigned t = atomicAdd(&g_done[b], 1u);
            const unsigned target = ((t >> 4) + 1u) << 4;
            while (*(volatile unsigned*)&g_done[b] < target) {}
            __threadfence();
            asm volatile("st.volatile.shared.u32 [%0], %1;"
                         :: "r"(sb + OFF_FLAG), "r"(1u) : "memory");
        }
    }

    // ---- Phase 2: main loop (identical to R16's engine) ----
    // Warp (mh, kq): rows [mh*32,+32) x cols [0,64), k16 slice kq.
    const int mh   = wid & 3;         // 0..3: 32-row band
    const int kq   = wid >> 2;        // 0..3: k16 slice
    const int ksub = kq >> 1;         // which 32-k A sub-tile
    const int grp  = kq & 1;          // which k16 group within the A sub-tile
    const int c    = lid & 3;
    const uint32_t sw   = (uint32_t)(lid >> 2) << 4;    // swizzle XOR (row&7)*16
    const uint32_t aRow = (uint32_t)(mh * 32 + (lid >> 2));
    const uint32_t bRow = (uint32_t)(lid >> 2);

    const uint32_t aOff0 = ((uint32_t)(grp * 64 + 8 * c)) ^ sw;   // a0: k 2c,2c+1
    const uint32_t aOff2 = aOff0 ^ 32u;                            // a2: k +8
    const uint32_t bOff0 = ((uint32_t)(kq * 32 + 4 * c)) ^ sw;    // b0: k 2c,2c+1
    const uint32_t bOff1 = bOff0 ^ 16u;                            // b1: k +8

    float acc[2][8][4];   // [mt 16-row tiles][nt 8-col tiles][frag] = 64 regs
    #pragma unroll
    for (int mt = 0; mt < 2; mt++)
        #pragma unroll
        for (int nt = 0; nt < 8; nt++)
            #pragma unroll
            for (int i = 0; i < 4; i++) acc[mt][nt][i] = 0.0f;

    int st = 0, ph = 0;
    for (int it = 0; it < NITER; it++) {
        MBARRIER_WAIT_PARITY(sb + OFF_FULLA + st * 8, ph);
        MBARRIER_WAIT_PARITY(sb + OFF_FULLW + st * 8, ph);
        const char* base  = smem + OFF_DATA + st * STAGE_BYTES;
        const char* aBase = base + ksub * A_SUB;
        const char* bBase = base + A_BYTES;

        // B fragments: 8 n-tiles x 2 LDS.32, raw f16x2, no conversion.
        uint32_t bf[8][2];
        #pragma unroll
        for (int nt = 0; nt < 8; nt++) {
            const char* rp = bBase + (bRow + nt * 8) * 128;
            bf[nt][0] = *reinterpret_cast<const uint32_t*>(rp + bOff0);
            bf[nt][1] = *reinterpret_cast<const uint32_t*>(rp + bOff1);
        }

        #pragma unroll
        for (int mt = 0; mt < 2; mt++) {
            const char* ap = aBase + (aRow + mt * 16) * 128;
            const float2 f0 = *reinterpret_cast<const float2*>(ap + aOff0);
            const float2 f1 = *reinterpret_cast<const float2*>(ap + 1024 + aOff0);
            const float2 f2 = *reinterpret_cast<const float2*>(ap + aOff2);
            const float2 f3 = *reinterpret_cast<const float2*>(ap + 1024 + aOff2);
            uint32_t af[4];
            CVT_F16X2(af[0], f0.x, f0.y);
            CVT_F16X2(af[1], f1.x, f1.y);
            CVT_F16X2(af[2], f2.x, f2.y);
            CVT_F16X2(af[3], f3.x, f3.y);
            #pragma unroll
            for (int nt = 0; nt < 8; nt++)
                MMA_F16(acc[mt][nt], af, bf[nt]);
        }

        // HMMA issue implies all this stage's LDS completed -> safe to recycle.
        __syncwarp();
        if (lid == 0) MBARRIER_ARRIVE(sb + OFF_EMPTY + st * 8);
        if (++st == NSTAGE) { st = 0; ph ^= 1; }
    }

    // ---------------- 4-way cross-k reduction + epilogue ----------------
    {
        asm volatile("bar.sync 1, 512;" ::: "memory");   // all loop reads done
        float* redBase = reinterpret_cast<float*>(smem + OFF_DATA);
        if (kq != 0) {
            float* myBuf = redBase + (mh * 3 + (kq - 1)) * 2048;
            #pragma unroll
            for (int mt = 0; mt < 2; mt++)
                #pragma unroll
                for (int nt = 0; nt < 8; nt++)
                    #pragma unroll
                    for (int i = 0; i < 4; i++)
                        myBuf[((mt * 8 + nt) * 4 + i) * 32 + lid] = acc[mt][nt][i];
        }
        asm volatile("bar.sync 1, 512;" ::: "memory");
        if (kq == 0) {
            const float* r0 = redBase + (mh * 3 + 0) * 2048;
            const float* r1 = redBase + (mh * 3 + 1) * 2048;
            const float* r2 = redBase + (mh * 3 + 2) * 2048;
            #pragma unroll
            for (int mt = 0; mt < 2; mt++)
                #pragma unroll
                for (int nt = 0; nt < 8; nt++)
                    #pragma unroll
                    for (int i = 0; i < 4; i++) {
                        const int j = ((mt * 8 + nt) * 4 + i) * 32 + lid;
                        acc[mt][nt][i] += r0[j] + r1[j] + r2[j];
                    }

            // c0,c1 -> (row = lane/4, cols 2*(lane%4)+{0,1}); c2,c3 -> row+8.
            const size_t rowBase = (size_t)b * kS + (size_t)tile * TILE_M
                                 + (size_t)(mh * 32) + (size_t)(lid >> 2);
            const int colBase = (lid & 3) * 2;
            #pragma unroll
            for (int mt = 0; mt < 2; mt++) {
                #pragma unroll
                for (int nt = 0; nt < 8; nt++) {
                    const size_t r0w = rowBase + mt * 16;
                    float* p0 = out + r0w * kOUT + nt * 8 + colBase;
                    float* p1 = out + (r0w + 8) * kOUT + nt * 8 + colBase;
                    *reinterpret_cast<float2*>(p0) =
                        make_float2(acc[mt][nt][0], acc[mt][nt][1]);
                    *reinterpret_cast<float2*>(p1) =
                        make_float2(acc[mt][nt][2], acc[mt][nt][3]);
                }
            }
        }
    }
}

}  // namespace mlora

// ============================================================================
// Host side
// ============================================================================

typedef CUresult (*PFN_encodeTiled)(
    CUtensorMap*, CUtensorMapDataType, cuuint32_t, void*,
    const cuuint64_t*, const cuuint64_t*, const cuuint32_t*, const cuuint32_t*,
    CUtensorMapInterleave, CUtensorMapSwizzle, CUtensorMapL2promotion,
    CUtensorMapFloatOOBfill);

extern "C" void kernel_launch(void* const* d_in, const int* in_sizes, int n_in,
                              void* d_out, int out_size) {
    (void)in_sizes; (void)n_in; (void)out_size;
    const float* x   = (const float*)d_in[0];
    const int*   ids = (const int*)  d_in[1];
    const float* w   = (const float*)d_in[2];
    float*       out = (float*)d_out;

    PFN_encodeTiled enc = nullptr;
    {
        void* p = nullptr;
        cudaDriverEntryPointQueryResult qr;
#if CUDART_VERSION >= 12050
        cudaGetDriverEntryPointByVersion("cuTensorMapEncodeTiled", &p, 12000,
                                         cudaEnableDefault, &qr);
#else
        cudaGetDriverEntryPoint("cuTensorMapEncodeTiled", &p, cudaEnableDefault, &qr);
#endif
        enc = (PFN_encodeTiled)p;
    }

    void* wf16 = nullptr;
    cudaGetSymbolAddress(&wf16, g_wf16);

    CUtensorMap mapX, mapW;
    {
        // x: [B, S, IN] fp32 contiguous; dim0 = IN. Box = 32 x 128 (128B rows,
        // SW128), L2 promotion 256B.
        cuuint64_t dims[3]    = {(cuuint64_t)mlora::kIN, (cuuint64_t)mlora::kS,
                                 (cuuint64_t)mlora::kB};
        cuuint64_t strides[2] = {(cuuint64_t)mlora::kIN * 4,
                                 (cuuint64_t)mlora::kS * mlora::kIN * 4};
        cuuint32_t box[3]     = {32, (cuuint32_t)mlora::TILE_M, 1};
        cuuint32_t es[3]      = {1, 1, 1};
        enc(&mapX, CU_TENSOR_MAP_DATA_TYPE_FLOAT32, 3, (void*)x,
            dims, strides, box, es,
            CU_TENSOR_MAP_INTERLEAVE_NONE, CU_TENSOR_MAP_SWIZZLE_128B,
            CU_TENSOR_MAP_L2_PROMOTION_L2_256B, CU_TENSOR_MAP_FLOAT_OOB_FILL_NONE);
    }
    {
        // wf16: [L, OUT, IN] f16 contiguous; dim0 = IN. Box = 64 x 64 (128B rows, SW128).
        cuuint64_t dims[3]    = {(cuuint64_t)mlora::kIN, (cuuint64_t)mlora::kOUT,
                                 (cuuint64_t)mlora::kL};
        cuuint64_t strides[2] = {(cuuint64_t)mlora::kIN * 2,
                                 (cuuint64_t)mlora::kOUT * mlora::kIN * 2};
        cuuint32_t box[3]     = {(cuuint32_t)mlora::TILE_K, (cuuint32_t)mlora::kOUT, 1};
        cuuint32_t es[3]      = {1, 1, 1};
        enc(&mapW, CU_TENSOR_MAP_DATA_TYPE_FLOAT16, 3, wf16,
            dims, strides, box, es,
            CU_TENSOR_MAP_INTERLEAVE_NONE, CU_TENSOR_MAP_SWIZZLE_128B,
            CU_TENSOR_MAP_L2_PROMOTION_L2_128B, CU_TENSOR_MAP_FLOAT_OOB_FILL_NONE);
    }

    cudaFuncSetAttribute(mlora::mlora_kernel,
                         cudaFuncAttributeMaxDynamicSharedMemorySize,
                         mlora::SMEM_TOTAL);

    const int grid = mlora::kB * (mlora::kS / mlora::TILE_M);  // 128
    mlora::mlora_kernel<<<grid, mlora::NTHREADS, mlora::SMEM_TOTAL>>>(
        mapX, mapW, ids, (const float4*)w, out);
}